// round 1
// baseline (speedup 1.0000x reference)
#include <cuda_runtime.h>

#define NC 256      // clusters
#define KK 16       // cluster size
#define DD 256      // embed dim
#define NN 4096     // NC*KK
#define MARGINF 1.0f
#define EPSF 1e-6f

__device__ int   g_pos_idx[NN];
__device__ int   g_neg_idx[NN];
__device__ float g_loss[NN];

// One CTA per cluster. 256 threads. Each thread handles 16 j-rows (j = tid + 256*m),
// computing dot(emb_i, emb_j) for all 16 cluster rows i kept in SMEM, plus sq[j] on the fly.
__global__ __launch_bounds__(256, 2)
void hardest_kernel(const float* __restrict__ emb) {
    const int c   = blockIdx.x;
    const int tid = threadIdx.x;

    __shared__ float Ei[KK][DD];        // 16 KB: cluster rows
    __shared__ float sqi[KK];
    __shared__ float distc[KK][KK];     // within-cluster distances (i x jj)
    __shared__ float rv[KK][8];         // per-warp neg candidates
    __shared__ int   ri[KK][8];

    const int jbase = c * KK;

    // Load cluster tile
    const float4* src = (const float4*)(emb + (size_t)jbase * DD);
    for (int idx = tid; idx < KK * DD / 4; idx += 256)
        ((float4*)Ei)[idx] = src[idx];
    __syncthreads();

    if (tid < KK) {
        float s = 0.f;
        #pragma unroll 8
        for (int d = 0; d < DD; d++) { float v = Ei[tid][d]; s += v * v; }
        sqi[tid] = s;
    }
    __syncthreads();

    // Per-thread hardest-negative trackers (per cluster row i)
    float bnv[KK];
    int   bni[KK];
    #pragma unroll
    for (int i = 0; i < KK; i++) { bnv[i] = 3.0e38f; bni[i] = 0x7fffffff; }

    for (int j = tid; j < NN; j += 256) {
        const float4* pj = (const float4*)(emb + (size_t)j * DD);
        float acc[KK];
        #pragma unroll
        for (int i = 0; i < KK; i++) acc[i] = 0.f;
        float sqj = 0.f;

        for (int q = 0; q < DD / 4; q++) {
            float4 v = __ldg(&pj[q]);
            sqj += v.x * v.x + v.y * v.y + v.z * v.z + v.w * v.w;
            #pragma unroll
            for (int i = 0; i < KK; i++) {
                float4 e = ((const float4*)(Ei[i]))[q];
                acc[i] += v.x * e.x + v.y * e.y + v.z * e.z + v.w * e.w;
            }
        }

        const int  jj        = j - jbase;
        const bool incluster = (unsigned)jj < (unsigned)KK;

        #pragma unroll
        for (int i = 0; i < KK; i++) {
            float d2   = sqi[i] + sqj - 2.f * acc[i];
            float dist = sqrtf(fmaxf(d2, 0.f));
            if (incluster) {
                distc[i][jj] = dist;
            } else {
                // j strictly ascending per thread -> strict < keeps first occurrence
                if (dist < bnv[i]) { bnv[i] = dist; bni[i] = j; }
            }
        }
    }

    // Warp-level reduce of negatives (tie-break: smallest index, matching jnp.argmin)
    const unsigned fullm = 0xffffffffu;
    #pragma unroll
    for (int i = 0; i < KK; i++) {
        float v  = bnv[i];
        int   ix = bni[i];
        #pragma unroll
        for (int off = 16; off; off >>= 1) {
            float ov = __shfl_xor_sync(fullm, v,  off);
            int   oi = __shfl_xor_sync(fullm, ix, off);
            if (ov < v || (ov == v && oi < ix)) { v = ov; ix = oi; }
        }
        if ((tid & 31) == 0) { rv[i][tid >> 5] = v; ri[i][tid >> 5] = ix; }
    }
    __syncthreads();

    if (tid < KK) {
        // Final negative across 8 warps
        float v  = rv[tid][0];
        int   ix = ri[tid][0];
        #pragma unroll
        for (int w = 1; w < 8; w++) {
            float ov = rv[tid][w];
            int   oi = ri[tid][w];
            if (ov < v || (ov == v && oi < ix)) { v = ov; ix = oi; }
        }
        g_neg_idx[jbase + tid] = ix;

        // Hardest positive: scan ascending, strict > keeps first max (jnp.argmax)
        float pv = distc[tid][0];
        int   pi = 0;
        #pragma unroll
        for (int jj = 1; jj < KK; jj++) {
            float d = distc[tid][jj];
            if (d > pv) { pv = d; pi = jj; }
        }
        g_pos_idx[jbase + tid] = jbase + pi;
    }
}

// One warp per row i: d_ap = ||e_i - e_pos + eps||, d_an = ||e_i - e_neg + eps||
__global__ void loss_kernel(const float* __restrict__ emb) {
    const int i    = blockIdx.x;
    const int lane = threadIdx.x;   // 32 threads

    const int p = g_pos_idx[i];
    const int n = g_neg_idx[i];

    const float4* ei = (const float4*)(emb + (size_t)i * DD);
    const float4* ep = (const float4*)(emb + (size_t)p * DD);
    const float4* en = (const float4*)(emb + (size_t)n * DD);

    float sp = 0.f, sn = 0.f;
    #pragma unroll
    for (int t = 0; t < 2; t++) {
        int q = lane + 32 * t;
        float4 a = __ldg(&ei[q]);
        float4 b = __ldg(&ep[q]);
        float4 d = __ldg(&en[q]);
        float x;
        x = a.x - b.x + EPSF; sp += x * x;
        x = a.y - b.y + EPSF; sp += x * x;
        x = a.z - b.z + EPSF; sp += x * x;
        x = a.w - b.w + EPSF; sp += x * x;
        x = a.x - d.x + EPSF; sn += x * x;
        x = a.y - d.y + EPSF; sn += x * x;
        x = a.z - d.z + EPSF; sn += x * x;
        x = a.w - d.w + EPSF; sn += x * x;
    }
    #pragma unroll
    for (int off = 16; off; off >>= 1) {
        sp += __shfl_xor_sync(0xffffffffu, sp, off);
        sn += __shfl_xor_sync(0xffffffffu, sn, off);
    }
    if (lane == 0) {
        float d_ap = sqrtf(sp);
        float d_an = sqrtf(sn);
        g_loss[i] = fmaxf(d_ap - d_an + MARGINF, 0.f);
    }
}

// Deterministic tree reduction of 4096 losses -> mean
__global__ void reduce_kernel(float* __restrict__ out) {
    __shared__ float sh[1024];
    const int t = threadIdx.x;
    float s = 0.f;
    #pragma unroll
    for (int k = 0; k < NN / 1024; k++)
        s += g_loss[t + 1024 * k];
    sh[t] = s;
    __syncthreads();
    for (int off = 512; off; off >>= 1) {
        if (t < off) sh[t] += sh[t + off];
        __syncthreads();
    }
    if (t == 0) out[0] = sh[0] * (1.0f / (float)NN);
}

extern "C" void kernel_launch(void* const* d_in, const int* in_sizes, int n_in,
                              void* d_out, int out_size) {
    const float* emb = (const float*)d_in[0];
    float* out = (float*)d_out;

    hardest_kernel<<<NC, 256>>>(emb);
    loss_kernel<<<NN, 32>>>(emb);
    reduce_kernel<<<1, 1024>>>(out);
}

// round 2
// speedup vs baseline: 1.4277x; 1.4277x over previous
#include <cuda_runtime.h>

#define NC 256      // clusters
#define KK 16       // cluster size
#define DD 256      // embed dim
#define NN 4096     // NC*KK
#define MARGINF 1.0f
#define EPSF 1e-6f

__device__ int   g_pos_idx[NN];
__device__ int   g_neg_idx[NN];
__device__ float g_loss[NN];

typedef unsigned long long u64;

// packed fp32x2 FMA (sm_10x): d = a*b + c elementwise on two fp32 lanes
__device__ __forceinline__ u64 ffma2(u64 a, u64 b, u64 c) {
    u64 d;
    asm("fma.rn.f32x2 %0, %1, %2, %3;" : "=l"(d) : "l"(a), "l"(b), "l"(c));
    return d;
}
__device__ __forceinline__ float f2_lo(u64 v) { return __uint_as_float((unsigned)(v & 0xffffffffu)); }
__device__ __forceinline__ float f2_hi(u64 v) { return __uint_as_float((unsigned)(v >> 32)); }
__device__ __forceinline__ float f2_sum(u64 v) { return f2_lo(v) + f2_hi(v); }

// One CTA per cluster. 256 threads, each computes a 16i x 4j dot tile.
// D dimension processed as fp32x2 pairs (natural packing from 128-bit loads).
__global__ __launch_bounds__(256, 1)
void hardest_kernel(const float* __restrict__ emb) {
    const int c   = blockIdx.x;
    const int tid = threadIdx.x;

    __shared__ float Ei[KK][DD];        // 16 KB cluster rows
    __shared__ float sqi[KK];
    __shared__ float distc[KK][KK];     // within-cluster distances
    __shared__ float rv[KK][8];
    __shared__ int   ri[KK][8];

    const int jbase = c * KK;

    // Load cluster tile
    const float4* src = (const float4*)(emb + (size_t)jbase * DD);
    for (int idx = tid; idx < KK * DD / 4; idx += 256)
        ((float4*)Ei)[idx] = src[idx];
    __syncthreads();

    if (tid < KK) {
        float s = 0.f;
        #pragma unroll 8
        for (int d = 0; d < DD; d++) { float v = Ei[tid][d]; s += v * v; }
        sqi[tid] = s;
    }
    __syncthreads();

    float bnv[KK];
    int   bni[KK];
    #pragma unroll
    for (int i = 0; i < KK; i++) { bnv[i] = 3.0e38f; bni[i] = 0x7fffffff; }

    // j chunks of 1024: thread owns j = m + tid + 256*r, r=0..3 (strictly ascending sequence)
    for (int m = 0; m < NN; m += 1024) {
        const ulonglong2* p0 = (const ulonglong2*)(emb + (size_t)(m + tid)       * DD);
        const ulonglong2* p1 = (const ulonglong2*)(emb + (size_t)(m + tid + 256) * DD);
        const ulonglong2* p2 = (const ulonglong2*)(emb + (size_t)(m + tid + 512) * DD);
        const ulonglong2* p3 = (const ulonglong2*)(emb + (size_t)(m + tid + 768) * DD);

        u64 acc[KK][4];
        #pragma unroll
        for (int i = 0; i < KK; i++)
            #pragma unroll
            for (int r = 0; r < 4; r++) acc[i][r] = 0ull;
        u64 sq2[4] = {0ull, 0ull, 0ull, 0ull};

        #pragma unroll 2
        for (int q = 0; q < DD / 4; q++) {
            ulonglong2 v0 = __ldg(p0 + q);
            ulonglong2 v1 = __ldg(p1 + q);
            ulonglong2 v2 = __ldg(p2 + q);
            ulonglong2 v3 = __ldg(p3 + q);

            sq2[0] = ffma2(v0.x, v0.x, sq2[0]); sq2[0] = ffma2(v0.y, v0.y, sq2[0]);
            sq2[1] = ffma2(v1.x, v1.x, sq2[1]); sq2[1] = ffma2(v1.y, v1.y, sq2[1]);
            sq2[2] = ffma2(v2.x, v2.x, sq2[2]); sq2[2] = ffma2(v2.y, v2.y, sq2[2]);
            sq2[3] = ffma2(v3.x, v3.x, sq2[3]); sq2[3] = ffma2(v3.y, v3.y, sq2[3]);

            #pragma unroll
            for (int i = 0; i < KK; i++) {
                ulonglong2 e = ((const ulonglong2*)(Ei[i]))[q];   // broadcast LDS.128
                acc[i][0] = ffma2(e.x, v0.x, acc[i][0]);
                acc[i][0] = ffma2(e.y, v0.y, acc[i][0]);
                acc[i][1] = ffma2(e.x, v1.x, acc[i][1]);
                acc[i][1] = ffma2(e.y, v1.y, acc[i][1]);
                acc[i][2] = ffma2(e.x, v2.x, acc[i][2]);
                acc[i][2] = ffma2(e.y, v2.y, acc[i][2]);
                acc[i][3] = ffma2(e.x, v3.x, acc[i][3]);
                acc[i][3] = ffma2(e.y, v3.y, acc[i][3]);
            }
        }

        // Epilogue for this chunk: r ascending keeps j strictly ascending per thread
        #pragma unroll
        for (int r = 0; r < 4; r++) {
            const int  j         = m + tid + 256 * r;
            const int  jj        = j - jbase;
            const bool incluster = (unsigned)jj < (unsigned)KK;
            const float sqj = f2_sum(sq2[r]);
            #pragma unroll
            for (int i = 0; i < KK; i++) {
                float dot  = f2_sum(acc[i][r]);
                float d2   = sqi[i] + sqj - 2.f * dot;
                float dist = sqrtf(fmaxf(d2, 0.f));
                if (incluster) {
                    distc[i][jj] = dist;
                } else {
                    if (dist < bnv[i]) { bnv[i] = dist; bni[i] = j; }
                }
            }
        }
    }

    // Warp reduce negatives (tie-break: smallest index = first occurrence, matching jnp.argmin)
    const unsigned fullm = 0xffffffffu;
    #pragma unroll
    for (int i = 0; i < KK; i++) {
        float v  = bnv[i];
        int   ix = bni[i];
        #pragma unroll
        for (int off = 16; off; off >>= 1) {
            float ov = __shfl_xor_sync(fullm, v,  off);
            int   oi = __shfl_xor_sync(fullm, ix, off);
            if (ov < v || (ov == v && oi < ix)) { v = ov; ix = oi; }
        }
        if ((tid & 31) == 0) { rv[i][tid >> 5] = v; ri[i][tid >> 5] = ix; }
    }
    __syncthreads();

    if (tid < KK) {
        float v  = rv[tid][0];
        int   ix = ri[tid][0];
        #pragma unroll
        for (int w = 1; w < 8; w++) {
            float ov = rv[tid][w];
            int   oi = ri[tid][w];
            if (ov < v || (ov == v && oi < ix)) { v = ov; ix = oi; }
        }
        g_neg_idx[jbase + tid] = ix;

        // Hardest positive: ascending scan, strict > keeps first max (jnp.argmax)
        float pv = distc[tid][0];
        int   pi = 0;
        #pragma unroll
        for (int jj = 1; jj < KK; jj++) {
            float d = distc[tid][jj];
            if (d > pv) { pv = d; pi = jj; }
        }
        g_pos_idx[jbase + tid] = jbase + pi;
    }
}

// One warp per row: exact fp32 recomputation of d_ap, d_an
__global__ void loss_kernel(const float* __restrict__ emb) {
    const int i    = blockIdx.x;
    const int lane = threadIdx.x;

    const int p = g_pos_idx[i];
    const int n = g_neg_idx[i];

    const float4* ei = (const float4*)(emb + (size_t)i * DD);
    const float4* ep = (const float4*)(emb + (size_t)p * DD);
    const float4* en = (const float4*)(emb + (size_t)n * DD);

    float sp = 0.f, sn = 0.f;
    #pragma unroll
    for (int t = 0; t < 2; t++) {
        int q = lane + 32 * t;
        float4 a = __ldg(&ei[q]);
        float4 b = __ldg(&ep[q]);
        float4 d = __ldg(&en[q]);
        float x;
        x = a.x - b.x + EPSF; sp += x * x;
        x = a.y - b.y + EPSF; sp += x * x;
        x = a.z - b.z + EPSF; sp += x * x;
        x = a.w - b.w + EPSF; sp += x * x;
        x = a.x - d.x + EPSF; sn += x * x;
        x = a.y - d.y + EPSF; sn += x * x;
        x = a.z - d.z + EPSF; sn += x * x;
        x = a.w - d.w + EPSF; sn += x * x;
    }
    #pragma unroll
    for (int off = 16; off; off >>= 1) {
        sp += __shfl_xor_sync(0xffffffffu, sp, off);
        sn += __shfl_xor_sync(0xffffffffu, sn, off);
    }
    if (lane == 0) {
        g_loss[i] = fmaxf(sqrtf(sp) - sqrtf(sn) + MARGINF, 0.f);
    }
}

__global__ void reduce_kernel(float* __restrict__ out) {
    __shared__ float sh[1024];
    const int t = threadIdx.x;
    float s = 0.f;
    #pragma unroll
    for (int k = 0; k < NN / 1024; k++)
        s += g_loss[t + 1024 * k];
    sh[t] = s;
    __syncthreads();
    for (int off = 512; off; off >>= 1) {
        if (t < off) sh[t] += sh[t + off];
        __syncthreads();
    }
    if (t == 0) out[0] = sh[0] * (1.0f / (float)NN);
}

extern "C" void kernel_launch(void* const* d_in, const int* in_sizes, int n_in,
                              void* d_out, int out_size) {
    const float* emb = (const float*)d_in[0];
    float* out = (float*)d_out;

    hardest_kernel<<<NC, 256>>>(emb);
    loss_kernel<<<NN, 32>>>(emb);
    reduce_kernel<<<1, 1024>>>(out);
}

// round 4
// speedup vs baseline: 5.5865x; 3.9130x over previous
#include <cuda_runtime.h>
#include <cuda_bf16.h>
#include <cstdint>

#define NC 256
#define KK 16
#define DD 256
#define NN 4096
#define MARGINF 1.0f
#define EPSF 1e-6f

#define TI 128
#define TJ 128
#define KC 64            // bf16 per k-chunk (128B rows)
#define NCHUNK 12        // effective K = 768
#define NTJ (NN / TJ)    // 32

#define STAGE_BYTES (TI*128 + TJ*128)   // 32 KB
#define SQ_OFF      (2 * STAGE_BYTES)   // 64 KB
#define DYN_SMEM    (SQ_OFF + 1024)

__device__ __nv_bfloat16 g_panel[(size_t)NN * 512];   // [hi(256) | lo(256)]
__device__ float g_sq[NN];
__device__ float g_cand_v[NN * NTJ];
__device__ int   g_cand_j[NN * NTJ];
__device__ int   g_pos_idx[NN];
__device__ float g_loss[NN];

#define LDSM4(r, a) \
    asm volatile("ldmatrix.sync.aligned.m8n8.x4.shared.b16 {%0,%1,%2,%3}, [%4];" \
        : "=r"((r)[0]), "=r"((r)[1]), "=r"((r)[2]), "=r"((r)[3]) : "r"(a))

#define MMA16816(c, a, b) \
    asm volatile("mma.sync.aligned.m16n8k16.row.col.f32.bf16.bf16.f32 " \
        "{%0,%1,%2,%3}, {%4,%5,%6,%7}, {%8,%9}, {%0,%1,%2,%3};" \
        : "+f"((c)[0]), "+f"((c)[1]), "+f"((c)[2]), "+f"((c)[3]) \
        : "r"((a)[0]), "r"((a)[1]), "r"((a)[2]), "r"((a)[3]), \
          "r"((b)[0]), "r"((b)[1]))

// ---------------- prep: fp32 -> [hi|lo] bf16 panel + sq ----------------
__global__ __launch_bounds__(256) void prep_kernel(const float* __restrict__ emb) {
    const int row  = blockIdx.x * 8 + (threadIdx.x >> 5);
    const int lane = threadIdx.x & 31;

    const float4* src = (const float4*)(emb + (size_t)row * DD);
    float4 a = __ldg(&src[lane * 2]);
    float4 b = __ldg(&src[lane * 2 + 1]);
    float x[8] = {a.x, a.y, a.z, a.w, b.x, b.y, b.z, b.w};

    alignas(16) __nv_bfloat16 hi[8];
    alignas(16) __nv_bfloat16 lo[8];
    float s = 0.f;
    #pragma unroll
    for (int t = 0; t < 8; t++) {
        __nv_bfloat16 h = __float2bfloat16(x[t]);
        hi[t] = h;
        lo[t] = __float2bfloat16(x[t] - __bfloat162float(h));
        s += x[t] * x[t];
    }
    __nv_bfloat16* dst = g_panel + (size_t)row * 512;
    *(uint4*)(dst + lane * 8)       = *(const uint4*)hi;
    *(uint4*)(dst + 256 + lane * 8) = *(const uint4*)lo;

    #pragma unroll
    for (int off = 16; off; off >>= 1)
        s += __shfl_xor_sync(0xffffffffu, s, off);
    if (lane == 0) g_sq[row] = s;
}

// ---------------- GEMM (HMMA) + fused hardest-pos/neg epilogue ----------------
__global__ __launch_bounds__(256)
void gemm_kernel() {
    extern __shared__ char dsm[];
    const int tid  = threadIdx.x;
    const int ti   = blockIdx.x;        // 0..31 (i tile)
    const int tj   = blockIdx.y;        // 0..31 (j tile)
    const int i0   = ti * TI;
    const int j0   = tj * TJ;
    const int wid  = tid >> 5, lane = tid & 31;
    const int wm   = wid >> 2, wn   = wid & 3;   // 2 x 4 warp grid

    const uint32_t sbase = (uint32_t)__cvta_generic_to_shared(dsm);
    float* s_sqi = (float*)(dsm + SQ_OFF);
    float* s_sqj = (float*)(dsm + SQ_OFF + 512);

    if (tid < 128) s_sqi[tid] = g_sq[i0 + tid];
    else           s_sqj[tid - 128] = g_sq[j0 + tid - 128];

    const char* gp = (const char*)g_panel;

    // global loads for chunk kc -> 4+4 uint4 per thread
    auto ldA = [&](int kc, uint4* r) {
        const int aoff = (kc < 8 ? kc : kc - 8) * KC;   // hi0-3, lo0-3, hi0-3
        #pragma unroll
        for (int it = 0; it < 4; it++) {
            const int idx = tid + 256 * it;
            const int row = idx >> 3, seg = idx & 7;
            r[it] = *(const uint4*)(gp + ((size_t)(i0 + row) * 512 + aoff + seg * 8) * 2);
        }
    };
    auto ldB = [&](int kc, uint4* r) {
        const int boff = (kc < 4 ? kc : (kc < 8 ? kc - 4 : kc)) * KC * 0
                       + ((kc < 4) ? kc : (kc < 8 ? kc - 4 : kc - 4)) * KC; // hi0-3, hi0-3, lo0-3
        #pragma unroll
        for (int it = 0; it < 4; it++) {
            const int idx = tid + 256 * it;
            const int row = idx >> 3, seg = idx & 7;
            r[it] = *(const uint4*)(gp + ((size_t)(j0 + row) * 512 + boff + seg * 8) * 2);
        }
    };
    // swizzled store into stage s
    auto stA = [&](int s, const uint4* r) {
        char* base = dsm + s * STAGE_BYTES;
        #pragma unroll
        for (int it = 0; it < 4; it++) {
            const int idx = tid + 256 * it;
            const int row = idx >> 3, seg = idx & 7;
            const int off = row * 128 + seg * 16;
            *(uint4*)(base + (off ^ ((off >> 3) & 0x70))) = r[it];
        }
    };
    auto stB = [&](int s, const uint4* r) {
        char* base = dsm + s * STAGE_BYTES + TI * 128;
        #pragma unroll
        for (int it = 0; it < 4; it++) {
            const int idx = tid + 256 * it;
            const int row = idx >> 3, seg = idx & 7;
            const int off = row * 128 + seg * 16;
            *(uint4*)(base + (off ^ ((off >> 3) & 0x70))) = r[it];
        }
    };

    uint4 bufA[4], bufB[4];
    ldA(0, bufA); ldB(0, bufB);
    stA(0, bufA); stB(0, bufB);
    __syncthreads();

    float acc[4][4][4];
    #pragma unroll
    for (int a = 0; a < 4; a++)
        #pragma unroll
        for (int b = 0; b < 4; b++)
            #pragma unroll
            for (int c = 0; c < 4; c++) acc[a][b][c] = 0.f;

    for (int kc = 0; kc < NCHUNK; kc++) {
        const int s = kc & 1;
        if (kc + 1 < NCHUNK) { ldA(kc + 1, bufA); ldB(kc + 1, bufB); }

        const uint32_t aBase = sbase + s * STAGE_BYTES;
        const uint32_t bBase = aBase + TI * 128;

        #pragma unroll
        for (int ks = 0; ks < 4; ks++) {
            uint32_t afr[4][4];
            #pragma unroll
            for (int fm = 0; fm < 4; fm++) {
                const int row = wm * 64 + fm * 16 + (lane & 15);
                const int ch  = (ks * 2 + (lane >> 4)) ^ (row & 7);
                LDSM4(afr[fm], aBase + row * 128 + ch * 16);
            }
            uint32_t bfr[2][4];
            #pragma unroll
            for (int g = 0; g < 2; g++) {
                const int row = wn * 32 + g * 16 + (lane & 7) + ((lane >> 4) & 1) * 8;
                const int ch  = (ks * 2 + ((lane >> 3) & 1)) ^ (row & 7);
                LDSM4(bfr[g], bBase + row * 128 + ch * 16);
            }
            #pragma unroll
            for (int fm = 0; fm < 4; fm++)
                #pragma unroll
                for (int fn = 0; fn < 4; fn++)
                    MMA16816(acc[fm][fn], afr[fm], &bfr[fn >> 1][(fn & 1) * 2]);
        }
        __syncthreads();
        if (kc + 1 < NCHUNK) { stA(s ^ 1, bufA); stB(s ^ 1, bufB); }
        __syncthreads();
    }

    // ---- fused epilogue: d2 + masked first-min / first-max ----
    float* r_nv = (float*)dsm;              // [128][4]
    int*   r_nj = (int*)(dsm + 2048);
    float* r_pv = (float*)(dsm + 4096);
    int*   r_pj = (int*)(dsm + 6144);
    const bool diag = (ti == tj);

    #pragma unroll
    for (int fm = 0; fm < 4; fm++) {
        #pragma unroll
        for (int h = 0; h < 2; h++) {
            const int rl = wm * 64 + fm * 16 + h * 8 + (lane >> 2);
            const int i  = i0 + rl;
            const int ci = i >> 4;
            const float sqi = s_sqi[rl];

            float bnv = 3.0e38f;  int bnj = 0x7fffffff;
            float bpv = -3.0e38f; int bpj = 0;

            #pragma unroll
            for (int fn = 0; fn < 4; fn++) {
                #pragma unroll
                for (int e = 0; e < 2; e++) {
                    const int cl = wn * 32 + fn * 8 + (lane & 3) * 2 + e;
                    const int j  = j0 + cl;
                    const float dot = acc[fm][fn][h * 2 + e];
                    const float d2  = sqi + s_sqj[cl] - 2.f * dot;
                    if (diag && ((j >> 4) == ci)) {
                        if (d2 > bpv) { bpv = d2; bpj = j; }
                    } else {
                        if (d2 < bnv) { bnv = d2; bnj = j; }
                    }
                }
            }
            // quad reduce (lanes differing in bits 0-1), index tie-break
            #pragma unroll
            for (int m = 1; m <= 2; m <<= 1) {
                float ov; int oj;
                ov = __shfl_xor_sync(0xffffffffu, bnv, m);
                oj = __shfl_xor_sync(0xffffffffu, bnj, m);
                if (ov < bnv || (ov == bnv && oj < bnj)) { bnv = ov; bnj = oj; }
                ov = __shfl_xor_sync(0xffffffffu, bpv, m);
                oj = __shfl_xor_sync(0xffffffffu, bpj, m);
                if (ov > bpv || (ov == bpv && oj < bpj)) { bpv = ov; bpj = oj; }
            }
            if ((lane & 3) == 0) {
                r_nv[rl * 4 + wn] = bnv; r_nj[rl * 4 + wn] = bnj;
                if (diag) { r_pv[rl * 4 + wn] = bpv; r_pj[rl * 4 + wn] = bpj; }
            }
        }
    }
    __syncthreads();

    if (tid < 128) {
        float v = r_nv[tid * 4]; int bj = r_nj[tid * 4];
        #pragma unroll
        for (int w = 1; w < 4; w++) {
            const float ov = r_nv[tid * 4 + w];
            const int   oj = r_nj[tid * 4 + w];
            if (ov < v || (ov == v && oj < bj)) { v = ov; bj = oj; }
        }
        g_cand_v[(size_t)(i0 + tid) * NTJ + tj] = v;
        g_cand_j[(size_t)(i0 + tid) * NTJ + tj] = bj;

        if (diag) {
            float pv = r_pv[tid * 4]; int pj = r_pj[tid * 4];
            #pragma unroll
            for (int w = 1; w < 4; w++) {
                const float ov = r_pv[tid * 4 + w];
                const int   oj = r_pj[tid * 4 + w];
                if (ov > pv || (ov == pv && oj < pj)) { pv = ov; pj = oj; }
            }
            g_pos_idx[i0 + tid] = pj;
        }
    }
}

// ---------------- finalize: reduce candidates + exact fp32 loss ----------------
__global__ void loss_kernel(const float* __restrict__ emb) {
    const int i    = blockIdx.x;
    const int lane = threadIdx.x;

    float v = g_cand_v[(size_t)i * NTJ + lane];
    int  bj = g_cand_j[(size_t)i * NTJ + lane];
    #pragma unroll
    for (int off = 16; off; off >>= 1) {
        const float ov = __shfl_xor_sync(0xffffffffu, v,  off);
        const int   oi = __shfl_xor_sync(0xffffffffu, bj, off);
        if (ov < v || (ov == v && oi < bj)) { v = ov; bj = oi; }
    }
    const int n = bj;
    const int p = g_pos_idx[i];

    const float4* ei = (const float4*)(emb + (size_t)i * DD);
    const float4* ep = (const float4*)(emb + (size_t)p * DD);
    const float4* en = (const float4*)(emb + (size_t)n * DD);

    float sp = 0.f, sn = 0.f;
    #pragma unroll
    for (int t = 0; t < 2; t++) {
        const int q = lane + 32 * t;
        float4 a = __ldg(&ei[q]);
        float4 b = __ldg(&ep[q]);
        float4 d = __ldg(&en[q]);
        float x;
        x = a.x - b.x + EPSF; sp += x * x;
        x = a.y - b.y + EPSF; sp += x * x;
        x = a.z - b.z + EPSF; sp += x * x;
        x = a.w - b.w + EPSF; sp += x * x;
        x = a.x - d.x + EPSF; sn += x * x;
        x = a.y - d.y + EPSF; sn += x * x;
        x = a.z - d.z + EPSF; sn += x * x;
        x = a.w - d.w + EPSF; sn += x * x;
    }
    #pragma unroll
    for (int off = 16; off; off >>= 1) {
        sp += __shfl_xor_sync(0xffffffffu, sp, off);
        sn += __shfl_xor_sync(0xffffffffu, sn, off);
    }
    if (lane == 0)
        g_loss[i] = fmaxf(sqrtf(sp) - sqrtf(sn) + MARGINF, 0.f);
}

__global__ void reduce_kernel(float* __restrict__ out) {
    __shared__ float sh[1024];
    const int t = threadIdx.x;
    float s = 0.f;
    #pragma unroll
    for (int k = 0; k < NN / 1024; k++) s += g_loss[t + 1024 * k];
    sh[t] = s;
    __syncthreads();
    for (int off = 512; off; off >>= 1) {
        if (t < off) sh[t] += sh[t + off];
        __syncthreads();
    }
    if (t == 0) out[0] = sh[0] * (1.0f / (float)NN);
}

extern "C" void kernel_launch(void* const* d_in, const int* in_sizes, int n_in,
                              void* d_out, int out_size) {
    const float* emb = (const float*)d_in[0];
    float* out = (float*)d_out;

    static bool attr_set = false;
    if (!attr_set) {
        cudaFuncSetAttribute(gemm_kernel, cudaFuncAttributeMaxDynamicSharedMemorySize, DYN_SMEM);
        attr_set = true;
    }

    prep_kernel<<<NN / 8, 256>>>(emb);
    gemm_kernel<<<dim3(NN / TI, NN / TJ), 256, DYN_SMEM>>>();
    loss_kernel<<<NN, 32>>>(emb);
    reduce_kernel<<<1, 1024>>>(out);
}

// round 5
// speedup vs baseline: 7.8622x; 1.4074x over previous
#include <cuda_runtime.h>
#include <cuda_bf16.h>
#include <cstdint>

#define NC 256
#define KK 16
#define DD 256
#define NN 4096
#define MARGINF 1.0f
#define EPSF 1e-6f

#define TI 128
#define TJ 128
#define KC 64            // bf16 per k-chunk (128B rows)
#define NCHUNK 12        // effective K = 768 (hi*hi + lo*hi + hi*lo)
#define NTI (NN / TI)    // 32
#define NTJ (NN / TJ)    // 32
#define NTILES (NTI * (NTI + 1) / 2)   // 528

#define STAGE_BYTES (TI*128 + TJ*128)   // 32 KB
#define SQ_OFF      (3 * STAGE_BYTES)   // 96 KB
#define DYN_SMEM    (SQ_OFF + 1024)

__device__ __nv_bfloat16 g_panel[(size_t)NN * 512];   // [hi(256) | lo(256)]
__device__ float g_sq[NN];
__device__ float g_cand_v[NN * NTJ];
__device__ int   g_cand_j[NN * NTJ];
__device__ int   g_pos_idx[NN];
__device__ unsigned long long g_sum_fix;
__device__ unsigned int g_done;

#define FIX_SCALE 17592186044416.0   // 2^44

#define LDSM4(r, a) \
    asm volatile("ldmatrix.sync.aligned.m8n8.x4.shared.b16 {%0,%1,%2,%3}, [%4];" \
        : "=r"((r)[0]), "=r"((r)[1]), "=r"((r)[2]), "=r"((r)[3]) : "r"(a))

#define MMA16816(c, a, b) \
    asm volatile("mma.sync.aligned.m16n8k16.row.col.f32.bf16.bf16.f32 " \
        "{%0,%1,%2,%3}, {%4,%5,%6,%7}, {%8,%9}, {%0,%1,%2,%3};" \
        : "+f"((c)[0]), "+f"((c)[1]), "+f"((c)[2]), "+f"((c)[3]) \
        : "r"((a)[0]), "r"((a)[1]), "r"((a)[2]), "r"((a)[3]), \
          "r"((b)[0]), "r"((b)[1]))

__device__ __forceinline__ void cp16(uint32_t dst, const void* src) {
    asm volatile("cp.async.cg.shared.global [%0], [%1], 16;" :: "r"(dst), "l"(src));
}
#define CP_COMMIT() asm volatile("cp.async.commit_group;")
#define CP_WAIT(n)  asm volatile("cp.async.wait_group %0;" :: "n"(n))

// ---------------- prep: fp32 -> [hi|lo] bf16 panel + sq + zero accumulators ----------------
__global__ __launch_bounds__(256) void prep_kernel(const float* __restrict__ emb) {
    if (blockIdx.x == 0 && threadIdx.x == 0) { g_sum_fix = 0ull; g_done = 0u; }

    const int row  = blockIdx.x * 8 + (threadIdx.x >> 5);
    const int lane = threadIdx.x & 31;

    const float4* src = (const float4*)(emb + (size_t)row * DD);
    float4 a = __ldg(&src[lane * 2]);
    float4 b = __ldg(&src[lane * 2 + 1]);
    float x[8] = {a.x, a.y, a.z, a.w, b.x, b.y, b.z, b.w};

    alignas(16) __nv_bfloat16 hi[8];
    alignas(16) __nv_bfloat16 lo[8];
    float s = 0.f;
    #pragma unroll
    for (int t = 0; t < 8; t++) {
        __nv_bfloat16 h = __float2bfloat16(x[t]);
        hi[t] = h;
        lo[t] = __float2bfloat16(x[t] - __bfloat162float(h));
        s += x[t] * x[t];
    }
    __nv_bfloat16* dst = g_panel + (size_t)row * 512;
    *(uint4*)(dst + lane * 8)       = *(const uint4*)hi;
    *(uint4*)(dst + 256 + lane * 8) = *(const uint4*)lo;

    #pragma unroll
    for (int off = 16; off; off >>= 1)
        s += __shfl_xor_sync(0xffffffffu, s, off);
    if (lane == 0) g_sq[row] = s;
}

// ---------------- triangular GEMM (HMMA, cp.async pipeline) + two-sided epilogue ----------------
__global__ __launch_bounds__(256, 2)
void gemm_kernel() {
    extern __shared__ char dsm[];
    const int tid = threadIdx.x;

    // decode blockIdx.x -> (ti, tj) with tj >= ti
    int rem = blockIdx.x, ti = 0;
    while (rem >= NTI - ti) { rem -= NTI - ti; ti++; }
    const int tj = ti + rem;

    const int i0 = ti * TI;
    const int j0 = tj * TJ;
    const int wid = tid >> 5, lane = tid & 31;
    const int wm  = wid >> 2, wn = wid & 3;   // 2 x 4 warp grid
    const bool diag = (ti == tj);

    const uint32_t sbase = (uint32_t)__cvta_generic_to_shared(dsm);
    float* s_sqi = (float*)(dsm + SQ_OFF);
    float* s_sqj = (float*)(dsm + SQ_OFF + 512);

    if (tid < 128) s_sqi[tid] = g_sq[i0 + tid];
    else           s_sqj[tid - 128] = g_sq[j0 + tid - 128];

    const char* gp = (const char*)g_panel;

    auto load_stage = [&](int kc, int s) {
        const uint32_t aBase = sbase + s * STAGE_BYTES;
        const uint32_t bBase = aBase + TI * 128;
        const int aoff = (kc < 8 ? kc : kc - 8) * KC;   // A: hi,lo,hi
        const int boff = (kc < 4 ? kc : kc - 4) * KC;   // B: hi,hi,lo
        #pragma unroll
        for (int it = 0; it < 4; it++) {
            const int idx = tid + 256 * it;
            const int row = idx >> 3, seg = idx & 7;
            const int off = row * 128 + seg * 16;
            cp16(aBase + (off ^ ((off >> 3) & 0x70)),
                 gp + ((size_t)(i0 + row) * 512 + aoff + seg * 8) * 2);
        }
        #pragma unroll
        for (int it = 0; it < 4; it++) {
            const int idx = tid + 256 * it;
            const int row = idx >> 3, seg = idx & 7;
            const int off = row * 128 + seg * 16;
            cp16(bBase + (off ^ ((off >> 3) & 0x70)),
                 gp + ((size_t)(j0 + row) * 512 + boff + seg * 8) * 2);
        }
        CP_COMMIT();
    };

    load_stage(0, 0);
    load_stage(1, 1);

    float acc[4][4][4];
    #pragma unroll
    for (int a = 0; a < 4; a++)
        #pragma unroll
        for (int b = 0; b < 4; b++)
            #pragma unroll
            for (int c = 0; c < 4; c++) acc[a][b][c] = 0.f;

    for (int kc = 0; kc < NCHUNK; kc++) {
        if (kc + 2 < NCHUNK) load_stage(kc + 2, (kc + 2) % 3);

        if (kc + 2 < NCHUNK)      { CP_WAIT(2); }
        else if (kc + 1 < NCHUNK) { CP_WAIT(1); }
        else                      { CP_WAIT(0); }
        __syncthreads();

        const uint32_t aBase = sbase + (kc % 3) * STAGE_BYTES;
        const uint32_t bBase = aBase + TI * 128;

        #pragma unroll
        for (int ks = 0; ks < 4; ks++) {
            uint32_t afr[4][4];
            #pragma unroll
            for (int fm = 0; fm < 4; fm++) {
                const int row = wm * 64 + fm * 16 + (lane & 15);
                const int ch  = (ks * 2 + (lane >> 4)) ^ (row & 7);
                LDSM4(afr[fm], aBase + row * 128 + ch * 16);
            }
            uint32_t bfr[2][4];
            #pragma unroll
            for (int g = 0; g < 2; g++) {
                const int row = wn * 32 + g * 16 + (lane & 7) + ((lane >> 4) & 1) * 8;
                const int ch  = (ks * 2 + ((lane >> 3) & 1)) ^ (row & 7);
                LDSM4(bfr[g], bBase + row * 128 + ch * 16);
            }
            #pragma unroll
            for (int fm = 0; fm < 4; fm++)
                #pragma unroll
                for (int fn = 0; fn < 4; fn++)
                    MMA16816(acc[fm][fn], afr[fm], &bfr[fn >> 1][(fn & 1) * 2]);
        }
        __syncthreads();
    }

    // ---- epilogue: row-side (all tiles) + col-side (off-diag) ----
    float* r_nv = (float*)dsm;               // [128][4]
    int*   r_nj = (int*)(dsm + 2048);
    float* r_pv = (float*)(dsm + 4096);
    int*   r_pj = (int*)(dsm + 6144);
    float* c_nv = (float*)(dsm + 8192);      // [128][2]
    int*   c_nj = (int*)(dsm + 9216);

    #pragma unroll
    for (int fm = 0; fm < 4; fm++) {
        #pragma unroll
        for (int h = 0; h < 2; h++) {
            const int rl = wm * 64 + fm * 16 + h * 8 + (lane >> 2);
            const int i  = i0 + rl;
            const int ci = i >> 4;
            const float sqi = s_sqi[rl];

            float bnv = 3.0e38f;  int bnj = 0x7fffffff;
            float bpv = -3.0e38f; int bpj = 0;

            #pragma unroll
            for (int fn = 0; fn < 4; fn++) {
                #pragma unroll
                for (int e = 0; e < 2; e++) {
                    const int cl = wn * 32 + fn * 8 + (lane & 3) * 2 + e;
                    const int j  = j0 + cl;
                    const float d2 = sqi + s_sqj[cl] - 2.f * acc[fm][fn][h * 2 + e];
                    if (diag && ((j >> 4) == ci)) {
                        if (d2 > bpv) { bpv = d2; bpj = j; }
                    } else {
                        if (d2 < bnv) { bnv = d2; bnj = j; }
                    }
                }
            }
            #pragma unroll
            for (int m = 1; m <= 2; m <<= 1) {
                float ov; int oj;
                ov = __shfl_xor_sync(0xffffffffu, bnv, m);
                oj = __shfl_xor_sync(0xffffffffu, bnj, m);
                if (ov < bnv || (ov == bnv && oj < bnj)) { bnv = ov; bnj = oj; }
                ov = __shfl_xor_sync(0xffffffffu, bpv, m);
                oj = __shfl_xor_sync(0xffffffffu, bpj, m);
                if (ov > bpv || (ov == bpv && oj < bpj)) { bpv = ov; bpj = oj; }
            }
            if ((lane & 3) == 0) {
                r_nv[rl * 4 + wn] = bnv; r_nj[rl * 4 + wn] = bnj;
                if (diag) { r_pv[rl * 4 + wn] = bpv; r_pj[rl * 4 + wn] = bpj; }
            }
        }
    }

    if (!diag) {
        #pragma unroll
        for (int fn = 0; fn < 4; fn++) {
            #pragma unroll
            for (int e = 0; e < 2; e++) {
                const int cl = wn * 32 + fn * 8 + (lane & 3) * 2 + e;
                const float sqj = s_sqj[cl];
                float bv = 3.0e38f; int bi = 0x7fffffff;
                #pragma unroll
                for (int fm = 0; fm < 4; fm++) {
                    #pragma unroll
                    for (int h = 0; h < 2; h++) {
                        const int rl = wm * 64 + fm * 16 + h * 8 + (lane >> 2);
                        const float d2 = s_sqi[rl] + sqj - 2.f * acc[fm][fn][h * 2 + e];
                        if (d2 < bv) { bv = d2; bi = i0 + rl; }
                    }
                }
                #pragma unroll
                for (int m = 4; m <= 16; m <<= 1) {
                    const float ov = __shfl_xor_sync(0xffffffffu, bv, m);
                    const int   oi = __shfl_xor_sync(0xffffffffu, bi, m);
                    if (ov < bv || (ov == bv && oi < bi)) { bv = ov; bi = oi; }
                }
                if ((lane >> 2) == 0) { c_nv[cl * 2 + wm] = bv; c_nj[cl * 2 + wm] = bi; }
            }
        }
    }
    __syncthreads();

    if (tid < 128) {
        float v = r_nv[tid * 4]; int bj = r_nj[tid * 4];
        #pragma unroll
        for (int w = 1; w < 4; w++) {
            const float ov = r_nv[tid * 4 + w];
            const int   oj = r_nj[tid * 4 + w];
            if (ov < v || (ov == v && oj < bj)) { v = ov; bj = oj; }
        }
        g_cand_v[(size_t)(i0 + tid) * NTJ + tj] = v;
        g_cand_j[(size_t)(i0 + tid) * NTJ + tj] = bj;

        if (diag) {
            float pv = r_pv[tid * 4]; int pj = r_pj[tid * 4];
            #pragma unroll
            for (int w = 1; w < 4; w++) {
                const float ov = r_pv[tid * 4 + w];
                const int   oj = r_pj[tid * 4 + w];
                if (ov > pv || (ov == pv && oj < pj)) { pv = ov; pj = oj; }
            }
            g_pos_idx[i0 + tid] = pj;
        }
    } else if (!diag) {
        const int c = tid - 128;
        float v = c_nv[c * 2]; int bi = c_nj[c * 2];
        const float ov = c_nv[c * 2 + 1];
        const int   oi = c_nj[c * 2 + 1];
        if (ov < v || (ov == v && oi < bi)) { v = ov; bi = oi; }
        g_cand_v[(size_t)(j0 + c) * NTJ + ti] = v;
        g_cand_j[(size_t)(j0 + c) * NTJ + ti] = bi;
    }
}

// ---------------- fused finalize: candidates -> exact loss -> deterministic mean ----------------
#define LB 64
__global__ __launch_bounds__(256) void loss_kernel(const float* __restrict__ emb,
                                                   float* __restrict__ out) {
    const int wid = threadIdx.x >> 5, lane = threadIdx.x & 31;
    __shared__ float warp_sum[8];

    float lsum = 0.f;
    #pragma unroll 1
    for (int r = 0; r < NN / (LB * 8); r++) {            // 8 rows per warp
        const int i = blockIdx.x * (NN / LB) + wid * (NN / (LB * 8)) + r;

        float v = g_cand_v[(size_t)i * NTJ + lane];
        int  bj = g_cand_j[(size_t)i * NTJ + lane];
        #pragma unroll
        for (int off = 16; off; off >>= 1) {
            const float ov = __shfl_xor_sync(0xffffffffu, v,  off);
            const int   oi = __shfl_xor_sync(0xffffffffu, bj, off);
            if (ov < v || (ov == v && oi < bj)) { v = ov; bj = oi; }
        }
        const int n = bj;
        const int p = g_pos_idx[i];

        const float4* ei = (const float4*)(emb + (size_t)i * DD);
        const float4* ep = (const float4*)(emb + (size_t)p * DD);
        const float4* en = (const float4*)(emb + (size_t)n * DD);

        float sp = 0.f, sn = 0.f;
        #pragma unroll
        for (int t = 0; t < 2; t++) {
            const int q = lane + 32 * t;
            float4 a = __ldg(&ei[q]);
            float4 b = __ldg(&ep[q]);
            float4 d = __ldg(&en[q]);
            float x;
            x = a.x - b.x + EPSF; sp += x * x;
            x = a.y - b.y + EPSF; sp += x * x;
            x = a.z - b.z + EPSF; sp += x * x;
            x = a.w - b.w + EPSF; sp += x * x;
            x = a.x - d.x + EPSF; sn += x * x;
            x = a.y - d.y + EPSF; sn += x * x;
            x = a.z - d.z + EPSF; sn += x * x;
            x = a.w - d.w + EPSF; sn += x * x;
        }
        #pragma unroll
        for (int off = 16; off; off >>= 1) {
            sp += __shfl_xor_sync(0xffffffffu, sp, off);
            sn += __shfl_xor_sync(0xffffffffu, sn, off);
        }
        if (lane == 0)
            lsum += fmaxf(sqrtf(sp) - sqrtf(sn) + MARGINF, 0.f);
    }
    if (lane == 0) warp_sum[wid] = lsum;
    __syncthreads();

    if (threadIdx.x == 0) {
        double s = 0.0;
        #pragma unroll
        for (int w = 0; w < 8; w++) s += (double)warp_sum[w];
        const unsigned long long fx = (unsigned long long)(s * FIX_SCALE + 0.5);
        atomicAdd(&g_sum_fix, fx);
        __threadfence();
        const unsigned done = atomicAdd(&g_done, 1u);
        if (done == LB - 1) {
            const unsigned long long tot = atomicAdd(&g_sum_fix, 0ull);
            out[0] = (float)((double)tot / FIX_SCALE / (double)NN);
        }
    }
}

extern "C" void kernel_launch(void* const* d_in, const int* in_sizes, int n_in,
                              void* d_out, int out_size) {
    const float* emb = (const float*)d_in[0];
    float* out = (float*)d_out;

    static bool attr_set = false;
    if (!attr_set) {
        cudaFuncSetAttribute(gemm_kernel, cudaFuncAttributeMaxDynamicSharedMemorySize, DYN_SMEM);
        attr_set = true;
    }

    prep_kernel<<<NN / 8, 256>>>(emb);
    gemm_kernel<<<NTILES, 256, DYN_SMEM>>>();
    loss_kernel<<<LB, 256>>>(emb, out);
}

// round 6
// speedup vs baseline: 10.8326x; 1.3778x over previous
#include <cuda_runtime.h>
#include <cuda_bf16.h>
#include <cstdint>

#define NC 256
#define KK 16
#define DD 256
#define NN 4096
#define MARGINF 1.0f
#define EPSF 1e-6f

#define TI 128
#define TJ 128
#define KC 64            // bf16 per k-chunk (128B rows)
#define NCHUNK 4         // K = 256 (hi-only)
#define NTI (NN / TI)    // 32
#define NTJ (NN / TJ)    // 32
#define NTILES (NTI * (NTI + 1) / 2)   // 528

#define STAGE_BYTES (TI*128 + TJ*128)   // 32 KB
#define SQ_OFF      (3 * STAGE_BYTES)   // 96 KB
#define DYN_SMEM    (SQ_OFF + 1024)

__device__ __nv_bfloat16 g_panel[(size_t)NN * 256];   // hi only
__device__ float g_sq[NN];
__device__ float g_cand_v[NN * NTJ];
__device__ int   g_cand_j[NN * NTJ];
__device__ int   g_pos_idx[NN];
__device__ unsigned long long g_sum_fix;
__device__ unsigned int g_done;

#define FIX_SCALE 17592186044416.0   // 2^44

#define LDSM4(r, a) \
    asm volatile("ldmatrix.sync.aligned.m8n8.x4.shared.b16 {%0,%1,%2,%3}, [%4];" \
        : "=r"((r)[0]), "=r"((r)[1]), "=r"((r)[2]), "=r"((r)[3]) : "r"(a))

#define MMA16816(c, a, b) \
    asm volatile("mma.sync.aligned.m16n8k16.row.col.f32.bf16.bf16.f32 " \
        "{%0,%1,%2,%3}, {%4,%5,%6,%7}, {%8,%9}, {%0,%1,%2,%3};" \
        : "+f"((c)[0]), "+f"((c)[1]), "+f"((c)[2]), "+f"((c)[3]) \
        : "r"((a)[0]), "r"((a)[1]), "r"((a)[2]), "r"((a)[3]), \
          "r"((b)[0]), "r"((b)[1]))

__device__ __forceinline__ void cp16(uint32_t dst, const void* src) {
    asm volatile("cp.async.cg.shared.global [%0], [%1], 16;" :: "r"(dst), "l"(src));
}
#define CP_COMMIT() asm volatile("cp.async.commit_group;")
#define CP_WAIT(n)  asm volatile("cp.async.wait_group %0;" :: "n"(n))

// ---------------- prep: fp32 -> bf16 hi panel + sq + zero accumulators ----------------
__global__ __launch_bounds__(256) void prep_kernel(const float* __restrict__ emb) {
    if (blockIdx.x == 0 && threadIdx.x == 0) { g_sum_fix = 0ull; g_done = 0u; }

    const int row  = blockIdx.x * 8 + (threadIdx.x >> 5);
    const int lane = threadIdx.x & 31;

    const float4* src = (const float4*)(emb + (size_t)row * DD);
    float4 a = __ldg(&src[lane * 2]);
    float4 b = __ldg(&src[lane * 2 + 1]);
    float x[8] = {a.x, a.y, a.z, a.w, b.x, b.y, b.z, b.w};

    alignas(16) __nv_bfloat16 hi[8];
    float s = 0.f;
    #pragma unroll
    for (int t = 0; t < 8; t++) {
        hi[t] = __float2bfloat16(x[t]);
        s += x[t] * x[t];
    }
    *(uint4*)(g_panel + (size_t)row * 256 + lane * 8) = *(const uint4*)hi;

    #pragma unroll
    for (int off = 16; off; off >>= 1)
        s += __shfl_xor_sync(0xffffffffu, s, off);
    if (lane == 0) g_sq[row] = s;
}

// ---------------- triangular GEMM (HMMA, cp.async pipeline) + two-sided epilogue ----------------
__global__ __launch_bounds__(256, 2)
void gemm_kernel() {
    extern __shared__ char dsm[];
    const int tid = threadIdx.x;

    // decode blockIdx.x -> (ti, tj) with tj >= ti
    int rem = blockIdx.x, ti = 0;
    while (rem >= NTI - ti) { rem -= NTI - ti; ti++; }
    const int tj = ti + rem;

    const int i0 = ti * TI;
    const int j0 = tj * TJ;
    const int wid = tid >> 5, lane = tid & 31;
    const int wm  = wid >> 2, wn = wid & 3;   // 2 x 4 warp grid
    const bool diag = (ti == tj);

    const uint32_t sbase = (uint32_t)__cvta_generic_to_shared(dsm);
    float* s_sqi = (float*)(dsm + SQ_OFF);
    float* s_sqj = (float*)(dsm + SQ_OFF + 512);

    if (tid < 128) s_sqi[tid] = g_sq[i0 + tid];
    else           s_sqj[tid - 128] = g_sq[j0 + tid - 128];

    const char* gp = (const char*)g_panel;

    auto load_stage = [&](int kc, int s) {
        const uint32_t aBase = sbase + s * STAGE_BYTES;
        const uint32_t bBase = aBase + TI * 128;
        const int koff = kc * KC;
        #pragma unroll
        for (int it = 0; it < 4; it++) {
            const int idx = tid + 256 * it;
            const int row = idx >> 3, seg = idx & 7;
            const int off = row * 128 + seg * 16;
            cp16(aBase + (off ^ ((off >> 3) & 0x70)),
                 gp + ((size_t)(i0 + row) * 256 + koff + seg * 8) * 2);
        }
        #pragma unroll
        for (int it = 0; it < 4; it++) {
            const int idx = tid + 256 * it;
            const int row = idx >> 3, seg = idx & 7;
            const int off = row * 128 + seg * 16;
            cp16(bBase + (off ^ ((off >> 3) & 0x70)),
                 gp + ((size_t)(j0 + row) * 256 + koff + seg * 8) * 2);
        }
        CP_COMMIT();
    };

    load_stage(0, 0);
    load_stage(1, 1);

    float acc[4][4][4];
    #pragma unroll
    for (int a = 0; a < 4; a++)
        #pragma unroll
        for (int b = 0; b < 4; b++)
            #pragma unroll
            for (int c = 0; c < 4; c++) acc[a][b][c] = 0.f;

    for (int kc = 0; kc < NCHUNK; kc++) {
        if (kc + 2 < NCHUNK) load_stage(kc + 2, (kc + 2) % 3);

        if (kc + 2 < NCHUNK)      { CP_WAIT(2); }
        else if (kc + 1 < NCHUNK) { CP_WAIT(1); }
        else                      { CP_WAIT(0); }
        __syncthreads();

        const uint32_t aBase = sbase + (kc % 3) * STAGE_BYTES;
        const uint32_t bBase = aBase + TI * 128;

        #pragma unroll
        for (int ks = 0; ks < 4; ks++) {
            uint32_t afr[4][4];
            #pragma unroll
            for (int fm = 0; fm < 4; fm++) {
                const int row = wm * 64 + fm * 16 + (lane & 15);
                const int ch  = (ks * 2 + (lane >> 4)) ^ (row & 7);
                LDSM4(afr[fm], aBase + row * 128 + ch * 16);
            }
            uint32_t bfr[2][4];
            #pragma unroll
            for (int g = 0; g < 2; g++) {
                const int row = wn * 32 + g * 16 + (lane & 7) + ((lane >> 4) & 1) * 8;
                const int ch  = (ks * 2 + ((lane >> 3) & 1)) ^ (row & 7);
                LDSM4(bfr[g], bBase + row * 128 + ch * 16);
            }
            #pragma unroll
            for (int fm = 0; fm < 4; fm++)
                #pragma unroll
                for (int fn = 0; fn < 4; fn++)
                    MMA16816(acc[fm][fn], afr[fm], &bfr[fn >> 1][(fn & 1) * 2]);
        }
        __syncthreads();
    }

    // ---- epilogue: row-side (all tiles) + col-side (off-diag) ----
    float* r_nv = (float*)dsm;               // [128][4]
    int*   r_nj = (int*)(dsm + 2048);
    float* r_pv = (float*)(dsm + 4096);
    int*   r_pj = (int*)(dsm + 6144);
    float* c_nv = (float*)(dsm + 8192);      // [128][2]
    int*   c_nj = (int*)(dsm + 9216);

    #pragma unroll
    for (int fm = 0; fm < 4; fm++) {
        #pragma unroll
        for (int h = 0; h < 2; h++) {
            const int rl = wm * 64 + fm * 16 + h * 8 + (lane >> 2);
            const int i  = i0 + rl;
            const int ci = i >> 4;
            const float sqi = s_sqi[rl];

            float bnv = 3.0e38f;  int bnj = 0x7fffffff;
            float bpv = -3.0e38f; int bpj = 0;

            #pragma unroll
            for (int fn = 0; fn < 4; fn++) {
                #pragma unroll
                for (int e = 0; e < 2; e++) {
                    const int cl = wn * 32 + fn * 8 + (lane & 3) * 2 + e;
                    const int j  = j0 + cl;
                    const float d2 = sqi + s_sqj[cl] - 2.f * acc[fm][fn][h * 2 + e];
                    if (diag && ((j >> 4) == ci)) {
                        if (d2 > bpv) { bpv = d2; bpj = j; }
                    } else {
                        if (d2 < bnv) { bnv = d2; bnj = j; }
                    }
                }
            }
            #pragma unroll
            for (int m = 1; m <= 2; m <<= 1) {
                float ov; int oj;
                ov = __shfl_xor_sync(0xffffffffu, bnv, m);
                oj = __shfl_xor_sync(0xffffffffu, bnj, m);
                if (ov < bnv || (ov == bnv && oj < bnj)) { bnv = ov; bnj = oj; }
                ov = __shfl_xor_sync(0xffffffffu, bpv, m);
                oj = __shfl_xor_sync(0xffffffffu, bpj, m);
                if (ov > bpv || (ov == bpv && oj < bpj)) { bpv = ov; bpj = oj; }
            }
            if ((lane & 3) == 0) {
                r_nv[rl * 4 + wn] = bnv; r_nj[rl * 4 + wn] = bnj;
                if (diag) { r_pv[rl * 4 + wn] = bpv; r_pj[rl * 4 + wn] = bpj; }
            }
        }
    }

    if (!diag) {
        #pragma unroll
        for (int fn = 0; fn < 4; fn++) {
            #pragma unroll
            for (int e = 0; e < 2; e++) {
                const int cl = wn * 32 + fn * 8 + (lane & 3) * 2 + e;
                const float sqj = s_sqj[cl];
                float bv = 3.0e38f; int bi = 0x7fffffff;
                #pragma unroll
                for (int fm = 0; fm < 4; fm++) {
                    #pragma unroll
                    for (int h = 0; h < 2; h++) {
                        const int rl = wm * 64 + fm * 16 + h * 8 + (lane >> 2);
                        const float d2 = s_sqi[rl] + sqj - 2.f * acc[fm][fn][h * 2 + e];
                        if (d2 < bv) { bv = d2; bi = i0 + rl; }
                    }
                }
                #pragma unroll
                for (int m = 4; m <= 16; m <<= 1) {
                    const float ov = __shfl_xor_sync(0xffffffffu, bv, m);
                    const int   oi = __shfl_xor_sync(0xffffffffu, bi, m);
                    if (ov < bv || (ov == bv && oi < bi)) { bv = ov; bi = oi; }
                }
                if ((lane >> 2) == 0) { c_nv[cl * 2 + wm] = bv; c_nj[cl * 2 + wm] = bi; }
            }
        }
    }
    __syncthreads();

    if (tid < 128) {
        float v = r_nv[tid * 4]; int bj = r_nj[tid * 4];
        #pragma unroll
        for (int w = 1; w < 4; w++) {
            const float ov = r_nv[tid * 4 + w];
            const int   oj = r_nj[tid * 4 + w];
            if (ov < v || (ov == v && oj < bj)) { v = ov; bj = oj; }
        }
        g_cand_v[(size_t)(i0 + tid) * NTJ + tj] = v;
        g_cand_j[(size_t)(i0 + tid) * NTJ + tj] = bj;

        if (diag) {
            float pv = r_pv[tid * 4]; int pj = r_pj[tid * 4];
            #pragma unroll
            for (int w = 1; w < 4; w++) {
                const float ov = r_pv[tid * 4 + w];
                const int   oj = r_pj[tid * 4 + w];
                if (ov > pv || (ov == pv && oj < pj)) { pv = ov; pj = oj; }
            }
            g_pos_idx[i0 + tid] = pj;
        }
    } else if (!diag) {
        const int c = tid - 128;
        float v = c_nv[c * 2]; int bi = c_nj[c * 2];
        const float ov = c_nv[c * 2 + 1];
        const int   oi = c_nj[c * 2 + 1];
        if (ov < v || (ov == v && oi < bi)) { v = ov; bi = oi; }
        g_cand_v[(size_t)(j0 + c) * NTJ + ti] = v;
        g_cand_j[(size_t)(j0 + c) * NTJ + ti] = bi;
    }
}

// ---------------- fused finalize: candidates -> exact loss -> deterministic mean ----------------
#define LB 64
__global__ __launch_bounds__(256) void loss_kernel(const float* __restrict__ emb,
                                                   float* __restrict__ out) {
    const int wid = threadIdx.x >> 5, lane = threadIdx.x & 31;
    __shared__ float warp_sum[8];

    float lsum = 0.f;
    #pragma unroll 1
    for (int r = 0; r < NN / (LB * 8); r++) {            // 8 rows per warp
        const int i = blockIdx.x * (NN / LB) + wid * (NN / (LB * 8)) + r;

        float v = g_cand_v[(size_t)i * NTJ + lane];
        int  bj = g_cand_j[(size_t)i * NTJ + lane];
        #pragma unroll
        for (int off = 16; off; off >>= 1) {
            const float ov = __shfl_xor_sync(0xffffffffu, v,  off);
            const int   oi = __shfl_xor_sync(0xffffffffu, bj, off);
            if (ov < v || (ov == v && oi < bj)) { v = ov; bj = oi; }
        }
        const int n = bj;
        const int p = g_pos_idx[i];

        const float4* ei = (const float4*)(emb + (size_t)i * DD);
        const float4* ep = (const float4*)(emb + (size_t)p * DD);
        const float4* en = (const float4*)(emb + (size_t)n * DD);

        float sp = 0.f, sn = 0.f;
        #pragma unroll
        for (int t = 0; t < 2; t++) {
            const int q = lane + 32 * t;
            float4 a = __ldg(&ei[q]);
            float4 b = __ldg(&ep[q]);
            float4 d = __ldg(&en[q]);
            float x;
            x = a.x - b.x + EPSF; sp += x * x;
            x = a.y - b.y + EPSF; sp += x * x;
            x = a.z - b.z + EPSF; sp += x * x;
            x = a.w - b.w + EPSF; sp += x * x;
            x = a.x - d.x + EPSF; sn += x * x;
            x = a.y - d.y + EPSF; sn += x * x;
            x = a.z - d.z + EPSF; sn += x * x;
            x = a.w - d.w + EPSF; sn += x * x;
        }
        #pragma unroll
        for (int off = 16; off; off >>= 1) {
            sp += __shfl_xor_sync(0xffffffffu, sp, off);
            sn += __shfl_xor_sync(0xffffffffu, sn, off);
        }
        if (lane == 0)
            lsum += fmaxf(sqrtf(sp) - sqrtf(sn) + MARGINF, 0.f);
    }
    if (lane == 0) warp_sum[wid] = lsum;
    __syncthreads();

    if (threadIdx.x == 0) {
        double s = 0.0;
        #pragma unroll
        for (int w = 0; w < 8; w++) s += (double)warp_sum[w];
        const unsigned long long fx = (unsigned long long)(s * FIX_SCALE + 0.5);
        atomicAdd(&g_sum_fix, fx);
        __threadfence();
        const unsigned done = atomicAdd(&g_done, 1u);
        if (done == LB - 1) {
            const unsigned long long tot = atomicAdd(&g_sum_fix, 0ull);
            out[0] = (float)((double)tot / FIX_SCALE / (double)NN);
        }
    }
}

extern "C" void kernel_launch(void* const* d_in, const int* in_sizes, int n_in,
                              void* d_out, int out_size) {
    const float* emb = (const float*)d_in[0];
    float* out = (float*)d_out;

    static bool attr_set = false;
    if (!attr_set) {
        cudaFuncSetAttribute(gemm_kernel, cudaFuncAttributeMaxDynamicSharedMemorySize, DYN_SMEM);
        attr_set = true;
    }

    prep_kernel<<<NN / 8, 256>>>(emb);
    gemm_kernel<<<NTILES, 256, DYN_SMEM>>>();
    loss_kernel<<<LB, 256>>>(emb, out);
}